// round 17
// baseline (speedup 1.0000x reference)
#include <cuda_runtime.h>
#include <cuda_fp16.h>
#include <math.h>
#include <stdint.h>

// ---------------------------------------------------------------------------
// AttSRU: T=512, B=32, S=512, D=512, fp32 I/O.
// Round 16: R15 + launch consolidation: (ss@Watt | ss@Whid) as one N=1024
// GEMM into a combined buffer; merged f2h converts; merged weight transposes.
// ---------------------------------------------------------------------------

namespace {
constexpr int  kT = 512, kB = 32, kS = 512, kD = 512;
constexpr long kTB   = (long)kT * kB;      // 16384 rows
constexpr long kTBD  = kTB * kD;           // 8388608
constexpr float kEPS = 1e-6f;

// fp16 scratch offsets (halfs)
constexpr long HF_PREV  = 0;
constexpr long HF_ENC   = HF_PREV  + kTBD;
constexpr long HF_PCTXR = HF_ENC   + kTBD;
constexpr long HF_PCTX  = HF_PCTXR + kTBD;
constexpr long HF_PCW   = HF_PCTX  + kTBD;   // pctx @ W_ctx   [B,S,D]
constexpr long HF_PCWT  = HF_PCW   + kTBD;   // transposed     [B,D,S]
constexpr long HF_SS    = HF_PCWT  + kTBD;
constexpr long HF_AH    = HF_SS    + kTBD;   // [TB,1024]: cols 0-511 attr, 512-1023 h1
constexpr long HF_ATT   = HF_AH    + 2 * kTBD;
constexpr long HF_SC    = HF_ATT   + kTBD;   // align scores (pre-scaled)
constexpr long HF_AV    = HF_SC    + kTBD;
constexpr long HF_H2    = HF_AV    + kTBD;
constexpr long HF_Z     = HF_H2    + kTBD;
constexpr long HF_HG    = HF_Z     + kTBD;
constexpr long HF_PL    = HF_HG    + kTBD;
constexpr long HF_PRE   = HF_PL    + kTBD;   // [TB,3D]
constexpr long HF_WTIN  = HF_PRE   + 3 * kTBD;
constexpr long HF_WTENC = HF_WTIN  + (long)3 * kD * kD;
constexpr long HF_WTATT = HF_WTENC + (long)kD * kD;   // WTATT and WTHID must be
constexpr long HF_WTHID = HF_WTATT + (long)kD * kD;   // contiguous (N=1024 GEMM)
constexpr long HF_WTCTX = HF_WTHID + (long)kD * kD;
constexpr long kSCH     = HF_WTCTX + (long)kD * kD;

constexpr long kSCF = (long)kB * kD;          // final scan state (fp32)

// fp16 GEMM smem: K-chunk 32 halfs/row, row stride 40 halfs (80B)
constexpr int RSH = 40;
constexpr int OPH = 128 * RSH;
constexpr int STG = 2 * OPH;
constexpr int GEMM_SMEM = 3 * STG * 2;        // 61440 B -> 2 CTAs/SM
}

__device__ float  g_scf[kSCF];
__device__ __half g_sch[kSCH];

// ---------------------------------------------------------------------------
// Helpers
// ---------------------------------------------------------------------------
__device__ __forceinline__ float warpSum(float v) {
#pragma unroll
    for (int o = 16; o; o >>= 1) v += __shfl_xor_sync(0xffffffffu, v, o);
    return v;
}
__device__ __forceinline__ float warpMax(float v) {
#pragma unroll
    for (int o = 16; o; o >>= 1) v = fmaxf(v, __shfl_xor_sync(0xffffffffu, v, o));
    return v;
}
__device__ __forceinline__ float2 blockSum2(float a, float b, float2* sh) {
    int w = threadIdx.x >> 5, l = threadIdx.x & 31, nw = blockDim.x >> 5;
    a = warpSum(a);
    b = warpSum(b);
    if (l == 0) sh[w] = make_float2(a, b);
    __syncthreads();
    float2 v = (l < nw) ? sh[l] : make_float2(0.f, 0.f);
    v.x = warpSum(v.x);
    v.y = warpSum(v.y);
    return v;
}
__device__ __forceinline__ float4 blockSum4(float a, float b, float c, float d,
                                            float4* sh) {
    int w = threadIdx.x >> 5, l = threadIdx.x & 31, nw = blockDim.x >> 5;
    a = warpSum(a); b = warpSum(b); c = warpSum(c); d = warpSum(d);
    if (l == 0) sh[w] = make_float4(a, b, c, d);
    __syncthreads();
    float4 v = (l < nw) ? sh[l] : make_float4(0.f, 0.f, 0.f, 0.f);
    v.x = warpSum(v.x); v.y = warpSum(v.y);
    v.z = warpSum(v.z); v.w = warpSum(v.w);
    return v;
}
__device__ __forceinline__ float blockMax(float v, float* sh) {
    int w = threadIdx.x >> 5, l = threadIdx.x & 31, nw = blockDim.x >> 5;
    v = warpMax(v);
    if (l == 0) sh[w] = v;
    __syncthreads();
    v = (l < nw) ? sh[l] : -INFINITY;
    v = warpMax(v);
    __syncthreads();
    return v;
}
__device__ __forceinline__ float blockSumS(float v, float* sh) {
    int w = threadIdx.x >> 5, l = threadIdx.x & 31, nw = blockDim.x >> 5;
    v = warpSum(v);
    if (l == 0) sh[w] = v;
    __syncthreads();
    v = (l < nw) ? sh[l] : 0.f;
    v = warpSum(v);
    return v;
}
__device__ __forceinline__ float sigm(float x) { return 1.f / (1.f + expf(-x)); }

__device__ __forceinline__ void ld4h(const __half* p, float& a, float& b,
                                     float& c, float& d) {
    uint2 r = *reinterpret_cast<const uint2*>(p);
    __half2 h0 = *reinterpret_cast<__half2*>(&r.x);
    __half2 h1 = *reinterpret_cast<__half2*>(&r.y);
    float2 f0 = __half22float2(h0), f1 = __half22float2(h1);
    a = f0.x; b = f0.y; c = f1.x; d = f1.y;
}
__device__ __forceinline__ void st4h(__half* p, float a, float b, float c, float d) {
    uint2 r;
    __half2 h0 = __floats2half2_rn(a, b), h1 = __floats2half2_rn(c, d);
    r.x = *reinterpret_cast<uint32_t*>(&h0);
    r.y = *reinterpret_cast<uint32_t*>(&h1);
    *reinterpret_cast<uint2*>(p) = r;
}

__device__ __forceinline__ void ldsm4(uint32_t& r0, uint32_t& r1,
                                      uint32_t& r2, uint32_t& r3, uint32_t addr) {
    asm volatile("ldmatrix.sync.aligned.m8n8.x4.shared.b16 {%0,%1,%2,%3}, [%4];"
                 : "=r"(r0), "=r"(r1), "=r"(r2), "=r"(r3) : "r"(addr));
}

// ---------------------------------------------------------------------------
// fp16 mma GEMM: C[M,N] = alpha * A[M,K] @ B[N,K]^T  (fp32 accum, fp16 out)
// Grid: (N/128, M/128, batch). Block: 256 (8 warps 4x2, warp tile 32x64).
// ---------------------------------------------------------------------------
__global__ __launch_bounds__(256, 2)
void gemm_h_kernel(const __half* __restrict__ A, const __half* __restrict__ B,
                   __half* __restrict__ C, int K,
                   long lda, long ldb, long ldc,
                   long sA, long sB, long sC, float alpha)
{
    extern __shared__ __half smh[];
    const uint32_t sb = (uint32_t)__cvta_generic_to_shared(smh);
    A += (long)blockIdx.z * sA;
    B += (long)blockIdx.z * sB;
    C += (long)blockIdx.z * sC;
    const int bm = blockIdx.y * 128, bn = blockIdx.x * 128;
    const int tid = threadIdx.x, wid = tid >> 5, lane = tid & 31;
    const int mw = (wid >> 1) * 32, nw = (wid & 1) * 64;
    const int lr = lane >> 2, lc = lane & 3;

    const int aoff = (mw + (lane & 15)) * RSH + (lane >> 4) * 8;
    const int boff0 = OPH + (nw + (lane & 7) + (lane >> 4) * 8) * RSH
                    + ((lane >> 3) & 1) * 8;

    const __half* gp[4];
    uint32_t dsto[4];
#pragma unroll
    for (int i = 0; i < 4; i++) {
        int id = tid + i * 256;
        bool isA = id < 512;
        int rid = id & 511;
        int row = rid >> 2, q = rid & 3;
        gp[i] = (isA ? A + (long)(bm + row) * lda
                     : B + (long)(bn + row) * ldb) + q * 8;
        dsto[i] = (isA ? 0u : (uint32_t)OPH) + (uint32_t)(row * RSH + q * 8);
    }
    const int nch = K >> 5;

    auto load_chunk = [&](int c, int s) {
        long ko = (long)c * 32;
        uint32_t base = (uint32_t)(s * STG);
#pragma unroll
        for (int i = 0; i < 4; i++) {
            uint32_t d = sb + (base + dsto[i]) * 2u;
            asm volatile("cp.async.cg.shared.global [%0], [%1], 16;"
                         :: "r"(d), "l"(gp[i] + ko));
        }
    };

    float acc[2][8][4];
#pragma unroll
    for (int i = 0; i < 2; i++)
#pragma unroll
        for (int j = 0; j < 8; j++)
#pragma unroll
            for (int v = 0; v < 4; v++) acc[i][j][v] = 0.f;

    load_chunk(0, 0);
    asm volatile("cp.async.commit_group;");
    if (nch > 1) {
        load_chunk(1, 1);
        asm volatile("cp.async.commit_group;");
    }

    for (int c = 0; c < nch; c++) {
        if (c + 1 < nch) asm volatile("cp.async.wait_group 1;");
        else             asm volatile("cp.async.wait_group 0;");
        __syncthreads();
        if (c + 2 < nch) {
            load_chunk(c + 2, (c + 2) % 3);
            asm volatile("cp.async.commit_group;");
        }
        const uint32_t stb = sb + (uint32_t)((c % 3) * STG) * 2u;
#pragma unroll
        for (int ks = 0; ks < 2; ks++) {
            const uint32_t kb = (uint32_t)(ks * 16) * 2u;
            uint32_t a[2][4];
#pragma unroll
            for (int im = 0; im < 2; im++)
                ldsm4(a[im][0], a[im][1], a[im][2], a[im][3],
                      stb + (uint32_t)(aoff + im * 16 * RSH) * 2u + kb);
#pragma unroll
            for (int p = 0; p < 4; p++) {
                uint32_t b0, b1, b2, b3;
                ldsm4(b0, b1, b2, b3, stb + (uint32_t)(boff0 + p * 16 * RSH) * 2u + kb);
#pragma unroll
                for (int im = 0; im < 2; im++) {
                    asm volatile(
                        "mma.sync.aligned.m16n8k16.row.col.f32.f16.f16.f32 "
                        "{%0,%1,%2,%3}, {%4,%5,%6,%7}, {%8,%9}, {%0,%1,%2,%3};"
                        : "+f"(acc[im][2 * p][0]), "+f"(acc[im][2 * p][1]),
                          "+f"(acc[im][2 * p][2]), "+f"(acc[im][2 * p][3])
                        : "r"(a[im][0]), "r"(a[im][1]), "r"(a[im][2]), "r"(a[im][3]),
                          "r"(b0), "r"(b1));
                    asm volatile(
                        "mma.sync.aligned.m16n8k16.row.col.f32.f16.f16.f32 "
                        "{%0,%1,%2,%3}, {%4,%5,%6,%7}, {%8,%9}, {%0,%1,%2,%3};"
                        : "+f"(acc[im][2 * p + 1][0]), "+f"(acc[im][2 * p + 1][1]),
                          "+f"(acc[im][2 * p + 1][2]), "+f"(acc[im][2 * p + 1][3])
                        : "r"(a[im][0]), "r"(a[im][1]), "r"(a[im][2]), "r"(a[im][3]),
                          "r"(b2), "r"(b3));
                }
            }
        }
    }

#pragma unroll
    for (int im = 0; im < 2; im++) {
        long r0 = (long)(bm + mw + im * 16 + lr);
#pragma unroll
        for (int jn = 0; jn < 8; jn++) {
            long col = bn + nw + jn * 8 + lc * 2;
            *reinterpret_cast<__half2*>(C + r0 * ldc + col) =
                __floats2half2_rn(acc[im][jn][0] * alpha, acc[im][jn][1] * alpha);
            *reinterpret_cast<__half2*>(C + (r0 + 8) * ldc + col) =
                __floats2half2_rn(acc[im][jn][2] * alpha, acc[im][jn][3] * alpha);
        }
    }
}

// ---------------------------------------------------------------------------
// fp32 -> fp16 convert for TWO tensors in one launch (same element count n4*4)
// ---------------------------------------------------------------------------
__global__ void f2h2_kernel(const float* __restrict__ in0, __half* __restrict__ out0,
                            const float* __restrict__ in1, __half* __restrict__ out1,
                            long n4)
{
    long i = (long)blockIdx.x * blockDim.x + threadIdx.x;
    const float* in;
    __half* out;
    if (i >= n4) {
        if (i >= 2 * n4) return;
        i -= n4;
        in = in1; out = out1;
    } else {
        in = in0; out = out0;
    }
    float4 v = reinterpret_cast<const float4*>(in)[i];
    reinterpret_cast<__half2*>(out)[i * 2]     = __floats2half2_rn(v.x, v.y);
    reinterpret_cast<__half2*>(out)[i * 2 + 1] = __floats2half2_rn(v.z, v.w);
}

// ---------------------------------------------------------------------------
// All 7 weight transposes in one launch.
// z 0..2: W_in column-slice z -> WTIN + z*kD*kD. z 3..6: square weights.
// ---------------------------------------------------------------------------
__global__ void transpose7_f2h_kernel(const float* __restrict__ W_in,
                                      const float* __restrict__ w0, const float* __restrict__ w1,
                                      const float* __restrict__ w2, const float* __restrict__ w3,
                                      __half* __restrict__ oIn,
                                      __half* __restrict__ o0, __half* __restrict__ o1,
                                      __half* __restrict__ o2, __half* __restrict__ o3)
{
    __shared__ float t[32][33];
    const float* in;
    __half* out;
    int C;
    int z = blockIdx.z;
    if (z < 3) {
        in = W_in + (long)z * kD;                 // column offset z*512 in [512,1536]
        out = oIn + (long)z * kD * kD;
        C = 3 * kD;
    } else {
        switch (z) {
            case 3: in = w0; out = o0; break;
            case 4: in = w1; out = o1; break;
            case 5: in = w2; out = o2; break;
            default: in = w3; out = o3; break;
        }
        C = kD;
    }
    int bx = blockIdx.x * 32, by = blockIdx.y * 32;
    int x = threadIdx.x, y = threadIdx.y;
#pragma unroll
    for (int i = 0; i < 32; i += 8) t[y + i][x] = in[(long)(by + y + i) * C + bx + x];
    __syncthreads();
#pragma unroll
    for (int i = 0; i < 32; i += 8)
        out[(long)(bx + y + i) * kD + by + x] = __float2half_rn(t[x][y + i]);
}

__global__ void transpose_h2h_kernel(const __half* __restrict__ in,
                                     __half* __restrict__ out,
                                     int R, int C, long sIn, long sOut)
{
    __shared__ __half t[32][34];
    in  += (long)blockIdx.z * sIn;
    out += (long)blockIdx.z * sOut;
    int bx = blockIdx.x * 32, by = blockIdx.y * 32;
    int x = threadIdx.x, y = threadIdx.y;
#pragma unroll
    for (int i = 0; i < 32; i += 8) t[y + i][x] = in[(long)(by + y + i) * C + bx + x];
    __syncthreads();
#pragma unroll
    for (int i = 0; i < 32; i += 8)
        out[(long)(bx + y + i) * R + by + x] = t[x][y + i];
}

// ---------------------------------------------------------------------------
// LN over 3D=1536 (fp16 in), split + sigmoid -> fp16 Z / HG / PL. block=384.
// ---------------------------------------------------------------------------
__global__ void ln_preact_kernel(const __half* __restrict__ pre,
                                 const float* __restrict__ g, const float* __restrict__ bb,
                                 __half* __restrict__ Z, __half* __restrict__ HG,
                                 __half* __restrict__ PL)
{
    __shared__ float2 sh[32];
    long row = blockIdx.x;
    int c = threadIdx.x * 4;
    float vx, vy, vz, vw;
    ld4h(pre + row * (3 * kD) + c, vx, vy, vz, vw);
    float s = vx + vy + vz + vw;
    float q = vx * vx + vy * vy + vz * vz + vw * vw;
    float2 sq = blockSum2(s, q, sh);
    const float invW = 1.f / (3 * kD);
    float m  = sq.x * invW;
    float rv = rsqrtf(sq.y * invW - m * m + kEPS);
    float n0 = g[c + 0] * ((vx - m) * rv) + bb[c + 0];
    float n1 = g[c + 1] * ((vy - m) * rv) + bb[c + 1];
    float n2 = g[c + 2] * ((vz - m) * rv) + bb[c + 2];
    float n3 = g[c + 3] * ((vw - m) * rv) + bb[c + 3];
    long rD = row * kD;
    if (c < kD) {
        st4h(Z + rD + c, sigm(n0), sigm(n1), sigm(n2), sigm(n3));
    } else if (c < 2 * kD) {
        st4h(HG + rD + (c - kD), sigm(n0), sigm(n1), sigm(n2), sigm(n3));
    } else {
        st4h(PL + rD + (c - 2 * kD), n0, n1, n2, n3);
    }
}

// LN over D=512: fp16 in (row stride ldx) -> fp16 out (dense). block=128.
__global__ void ln512h_kernel(const __half* __restrict__ x, __half* __restrict__ out,
                              const float* __restrict__ g, const float* __restrict__ b,
                              long ldx)
{
    __shared__ float2 sh[32];
    long row = blockIdx.x;
    int c = threadIdx.x * 4;
    float vx, vy, vz, vw;
    ld4h(x + row * ldx + c, vx, vy, vz, vw);
    float s = vx + vy + vz + vw;
    float q = vx * vx + vy * vy + vz * vz + vw * vw;
    float2 sq = blockSum2(s, q, sh);
    const float invW = 1.f / kD;
    float m  = sq.x * invW;
    float rv = rsqrtf(sq.y * invW - m * m + kEPS);
    st4h(out + row * kD + c,
         g[c + 0] * ((vx - m) * rv) + b[c + 0],
         g[c + 1] * ((vy - m) * rv) + b[c + 1],
         g[c + 2] * ((vz - m) * rv) + b[c + 2],
         g[c + 3] * ((vw - m) * rv) + b[c + 3]);
}

// SRU scan over half2 lanes: fp32 state, fp16 ss out, fp32 final state.
__global__ __launch_bounds__(64)
void scan_kernel(const __half2* __restrict__ Z, const __half2* __restrict__ PL,
                 const float* __restrict__ h0, __half2* __restrict__ ssh,
                 float* __restrict__ sslast)
{
    constexpr int BATCH = 16;
    int idx = blockIdx.x * 64 + threadIdx.x;
    float2 s = reinterpret_cast<const float2*>(h0)[idx];
    const long stride = (long)kB * kD / 2;
    long off = idx;
    for (int g = 0; g < kT / BATCH; g++) {
        __half2 z[BATCH], p[BATCH];
#pragma unroll
        for (int j = 0; j < BATCH; j++) z[j] = Z[off + j * stride];
#pragma unroll
        for (int j = 0; j < BATCH; j++) p[j] = PL[off + j * stride];
#pragma unroll
        for (int j = 0; j < BATCH; j++) {
            float2 zf = __half22float2(z[j]);
            float2 pf = __half22float2(p[j]);
            s.x = (1.f - zf.x) * s.x + zf.x * pf.x;
            s.y = (1.f - zf.y) * s.y + zf.y * pf.y;
            ssh[off + j * stride] = __floats2half2_rn(s.x, s.y);
        }
        off += (long)BATCH * stride;
    }
    reinterpret_cast<float2*>(sslast)[idx] = s;
}

// Masked softmax over S=512: fp16 pre-scaled scores in; fp32 p_attn + fp16 probs.
__global__ void softmax_kernel(const __half* __restrict__ sc, __half* __restrict__ avh,
                               float* __restrict__ pattn, const int* __restrict__ mlen)
{
    __shared__ float sh[32];
    long row = blockIdx.x;                 // b*T + t
    int b = (int)(row / kT), t = (int)(row % kT);
    int ml = mlen[b];
    int c = threadIdx.x * 4;
    float x0, x1, x2, x3;
    ld4h(sc + row * kS + c, x0, x1, x2, x3);
    float mx = -INFINITY;
    if (c + 0 < ml) mx = fmaxf(mx, x0);
    if (c + 1 < ml) mx = fmaxf(mx, x1);
    if (c + 2 < ml) mx = fmaxf(mx, x2);
    if (c + 3 < ml) mx = fmaxf(mx, x3);
    mx = blockMax(mx, sh);
    float e0 = (c + 0 < ml) ? expf(x0 - mx) : 0.f;
    float e1 = (c + 1 < ml) ? expf(x1 - mx) : 0.f;
    float e2 = (c + 2 < ml) ? expf(x2 - mx) : 0.f;
    float e3 = (c + 3 < ml) ? expf(x3 - mx) : 0.f;
    float sum = blockSumS(e0 + e1 + e2 + e3, sh);
    float is = 1.f / sum;
    float4 o = make_float4(e0 * is, e1 * is, e2 * is, e3 * is);
    *reinterpret_cast<float4*>(pattn + ((long)t * kB + b) * kS + c) = o;
    st4h(avh + row * kS + c, o.x, o.y, o.z, o.w);
}

// out = (1-hg)*tanh(LN(h1)+LN(h2)) + hg*prev
// h1 row stride ldh1 (combined AH buffer); h2, HG dense fp16; prev/out fp32.
__global__ void final_kernel(const __half* __restrict__ h1, const __half* __restrict__ h2,
                             const __half* __restrict__ HG, const float* __restrict__ prev,
                             const float* __restrict__ g_h, const float* __restrict__ b_h,
                             const float* __restrict__ g_c, const float* __restrict__ b_c,
                             float* __restrict__ out, long ldh1)
{
    __shared__ float4 sh[32];
    long row = blockIdx.x;
    int c = threadIdx.x * 4;
    float ax, ay, az, aw, dx, dy, dz, dw;
    ld4h(h1 + row * ldh1 + c, ax, ay, az, aw);
    ld4h(h2 + row * kD + c, dx, dy, dz, dw);
    float s1 = ax + ay + az + aw;
    float q1 = ax * ax + ay * ay + az * az + aw * aw;
    float s2 = dx + dy + dz + dw;
    float q2 = dx * dx + dy * dy + dz * dz + dw * dw;
    float4 r4 = blockSum4(s1, q1, s2, q2, sh);
    const float invW = 1.f / kD;
    float m1 = r4.x * invW, r1 = rsqrtf(r4.y * invW - m1 * m1 + kEPS);
    float m2 = r4.z * invW, r2 = rsqrtf(r4.w * invW - m2 * m2 + kEPS);
    float h0, h1v, h2v, h3;
    ld4h(HG + row * kD + c, h0, h1v, h2v, h3);
    float4 pv = *reinterpret_cast<const float4*>(prev + row * kD + c);
    float t0 = tanhf(g_h[c + 0] * ((ax - m1) * r1) + b_h[c + 0] +
                     g_c[c + 0] * ((dx - m2) * r2) + b_c[c + 0]);
    float t1 = tanhf(g_h[c + 1] * ((ay - m1) * r1) + b_h[c + 1] +
                     g_c[c + 1] * ((dy - m2) * r2) + b_c[c + 1]);
    float t2 = tanhf(g_h[c + 2] * ((az - m1) * r1) + b_h[c + 2] +
                     g_c[c + 2] * ((dz - m2) * r2) + b_c[c + 2]);
    float t3 = tanhf(g_h[c + 3] * ((aw - m1) * r1) + b_h[c + 3] +
                     g_c[c + 3] * ((dw - m2) * r2) + b_c[c + 3]);
    float4 o;
    o.x = (1.f - h0)  * t0 + h0  * pv.x;
    o.y = (1.f - h1v) * t1 + h1v * pv.y;
    o.z = (1.f - h2v) * t2 + h2v * pv.z;
    o.w = (1.f - h3)  * t3 + h3  * pv.w;
    *reinterpret_cast<float4*>(out + row * kD + c) = o;
}

// ---------------------------------------------------------------------------
// Launch
// ---------------------------------------------------------------------------
extern "C" void kernel_launch(void* const* d_in, const int* in_sizes, int n_in,
                              void* d_out, int out_size)
{
    int i_prev = -1, i_enc = -1, i_hidden = -1, i_ml = -1, i_Win = -1;
    int w4[4] = {-1, -1, -1, -1}; int n4 = 0;
    int p2[2] = {-1, -1};         int np = 0;
    int v8[8] = {-1, -1, -1, -1, -1, -1, -1, -1}; int nv = 0;
    for (int i = 0; i < n_in; i++) {
        switch (in_sizes[i]) {
            case 8388608: if (i_prev < 0) i_prev = i; else i_enc = i; break;
            case 16384:   i_hidden = i; break;
            case 32:      i_ml = i; break;
            case 786432:  i_Win = i; break;
            case 262144:  if (n4 < 4) w4[n4++] = i; break;
            case 1536:    if (np < 2) p2[np++] = i; break;
            case 512:     if (nv < 8) v8[nv++] = i; break;
            default: break;
        }
    }
    const float* prev   = (const float*)d_in[i_prev];
    const float* hidden = (const float*)d_in[i_hidden];
    const float* enc    = (const float*)d_in[i_enc];
    const int*   mlen   = (const int*)d_in[i_ml];
    const float* W_in   = (const float*)d_in[i_Win];
    const float* W_enc  = (const float*)d_in[w4[0]];
    const float* W_att  = (const float*)d_in[w4[1]];
    const float* W_hid  = (const float*)d_in[w4[2]];
    const float* W_ctx  = (const float*)d_in[w4[3]];
    const float* g_pre  = (const float*)d_in[p2[0]];
    const float* b_pre  = (const float*)d_in[p2[1]];
    const float* g_enc  = (const float*)d_in[v8[0]];
    const float* b_enc  = (const float*)d_in[v8[1]];
    const float* g_att  = (const float*)d_in[v8[2]];
    const float* b_att  = (const float*)d_in[v8[3]];
    const float* g_h    = (const float*)d_in[v8[4]];
    const float* b_h    = (const float*)d_in[v8[5]];
    const float* g_c    = (const float*)d_in[v8[6]];
    const float* b_c    = (const float*)d_in[v8[7]];

    float* sf = nullptr;
    __half* sh = nullptr;
    cudaGetSymbolAddress((void**)&sf, g_scf);
    cudaGetSymbolAddress((void**)&sh, g_sch);

    float* out       = (float*)d_out;            // [T,B,D]
    float* out_hid   = out + kTBD;               // [B,D]
    float* out_pattn = out_hid + (long)kB * kD;  // [T,B,S]

    cudaFuncSetAttribute(gemm_h_kernel,
                         cudaFuncAttributeMaxDynamicSharedMemorySize, GEMM_SMEM);

    dim3 tb(32, 8);
    const float invsq = rsqrtf((float)kD);
    const long bDS = (long)kB * kD;

    cudaStream_t s1;
    cudaStreamCreateWithFlags(&s1, cudaStreamNonBlocking);
    cudaEvent_t eW, eP, eQ;
    cudaEventCreateWithFlags(&eW, cudaEventDisableTiming);
    cudaEventCreateWithFlags(&eP, cudaEventDisableTiming);
    cudaEventCreateWithFlags(&eQ, cudaEventDisableTiming);

    // -- main: both converts + all weight transposes (consolidated) --
    f2h2_kernel<<<16384, 256>>>(prev, sh + HF_PREV, enc, sh + HF_ENC, kTBD / 4);
    transpose7_f2h_kernel<<<dim3(16, 16, 7), tb>>>(
        W_in, W_enc, W_att, W_hid, W_ctx,
        sh + HF_WTIN, sh + HF_WTENC, sh + HF_WTATT, sh + HF_WTHID, sh + HF_WTCTX);
    cudaEventRecord(eW, 0);

    // -- side stream: enc chain + pcw = pctx @ W_ctx (reassociated) --
    cudaStreamWaitEvent(s1, eW, 0);
    gemm_h_kernel<<<dim3(4, 128, 1), 256, GEMM_SMEM, s1>>>(
        sh + HF_ENC, sh + HF_WTENC, sh + HF_PCTXR, 512, 512, 512, 512, 0, 0, 0, 1.f);
    ln512h_kernel<<<(unsigned)kTB, 128, 0, s1>>>(sh + HF_PCTXR, sh + HF_PCTX,
                                                 g_enc, b_enc, kD);
    cudaEventRecord(eP, s1);                     // pctx ready (score GEMM gate)
    gemm_h_kernel<<<dim3(4, 128, 1), 256, GEMM_SMEM, s1>>>(
        sh + HF_PCTX, sh + HF_WTCTX, sh + HF_PCW, 512, 512, 512, 512, 0, 0, 0, 1.f);
    transpose_h2h_kernel<<<dim3(16, 16, 32), tb, 0, s1>>>(
        sh + HF_PCW, sh + HF_PCWT, kS, kD, (long)kS * kD, (long)kD * kS);
    cudaEventRecord(eQ, s1);                     // pcwT ready (h2 GEMM gate)

    // -- main: preact chain --
    gemm_h_kernel<<<dim3(12, 128, 1), 256, GEMM_SMEM>>>(
        sh + HF_PREV, sh + HF_WTIN, sh + HF_PRE, 512, 512, 512, 1536, 0, 0, 0, 1.f);
    ln_preact_kernel<<<(unsigned)kTB, 384>>>(sh + HF_PRE, g_pre, b_pre,
                                             sh + HF_Z, sh + HF_HG, sh + HF_PL);
    scan_kernel<<<128, 64>>>(reinterpret_cast<__half2*>(sh + HF_Z),
                             reinterpret_cast<__half2*>(sh + HF_PL), hidden,
                             reinterpret_cast<__half2*>(sh + HF_SS), sf);
    // combined GEMM: [attr | h1] = ss @ [W_att | W_hid]  (N=1024, one launch)
    gemm_h_kernel<<<dim3(8, 128, 1), 256, GEMM_SMEM>>>(
        sh + HF_SS, sh + HF_WTATT, sh + HF_AH, 512, 512, 512, 1024, 0, 0, 0, 1.f);
    ln512h_kernel<<<(unsigned)kTB, 128>>>(sh + HF_AH, sh + HF_ATT, g_att, b_att, 1024);

    // -- main: attention chain --
    cudaStreamWaitEvent(0, eP, 0);
    gemm_h_kernel<<<dim3(4, 4, 32), 256, GEMM_SMEM>>>(
        sh + HF_ATT, sh + HF_PCTX, sh + HF_SC, 512,
        bDS, 512, 512, kD, (long)kS * kD, (long)kT * kS, invsq);
    softmax_kernel<<<(unsigned)(kB * kT), 128>>>(sh + HF_SC, sh + HF_AV,
                                                 out_pattn, mlen);
    cudaStreamWaitEvent(0, eQ, 0);
    gemm_h_kernel<<<dim3(4, 4, 32), 256, GEMM_SMEM>>>(
        sh + HF_AV, sh + HF_PCWT, sh + HF_H2, 512,
        512, 512, bDS, (long)kT * kS, (long)kD * kS, kD, invsq);

    // final blend (h1 = AH cols 512..1023, stride 1024)
    final_kernel<<<(unsigned)kTB, 128>>>(sh + HF_AH + kD, sh + HF_H2, sh + HF_HG,
                                         prev, g_h, b_h, g_c, b_c, out, 1024);
    cudaMemcpyAsync(out_hid, sf, (size_t)kB * kD * sizeof(float),
                    cudaMemcpyDeviceToDevice, 0);
    // (stream/events intentionally leaked: destroying mid-capture invalidates it)
}